// round 1
// baseline (speedup 1.0000x reference)
#include <cuda_runtime.h>
#include <cuda_bf16.h>
#include <cstdint>

// Problem constants (fixed shapes)
#define NN 4096
#define FF 128
#define HEADS 8
#define UU 8
#define NCOL 160        // 80 hi cols + 80 lo cols
#define KC 64           // K chunk for GEMM

// ---------------- device scratch (no allocations allowed) ----------------
__device__ __nv_bfloat16 g_Xp[NCOL * NN];   // [col][node], col-major over nodes (1.31 MB)
__device__ float g_el[HEADS * NN];          // e_left per head/node

// ---------------- prep kernel: build Xp and e_l ----------------
// block = 128 threads = 16 nodes x 8 heads; grid = 256 blocks
#define WS 1036   // padded per-head W stride (floats) -> conflict-free float4 reads
__global__ __launch_bounds__(128) void gat_build(
    const float* __restrict__ H, const float* __restrict__ W,
    const float* __restrict__ al, const float* __restrict__ ar)
{
    __shared__ float sW[HEADS * WS];     // 8*1036*4 = 33.2 KB
    __shared__ float sH[16 * 129];       // 8.26 KB
    __shared__ float sal[64], sar[64];

    const int tid = threadIdx.x;
    // stage W [8][128][8]
    for (int i = tid; i < HEADS * FF * UU; i += 128) {
        int h = i >> 10;          // /1024
        int rem = i & 1023;
        sW[h * WS + rem] = W[i];
    }
    if (tid < 64) { sal[tid] = al[tid]; sar[tid] = ar[tid]; }
    // stage H tile: 16 nodes x 128 feats (coalesced)
    const int nodeBase = blockIdx.x * 16;
    for (int i = tid; i < 16 * FF; i += 128) {
        int n = i >> 7, f = i & 127;
        sH[n * 129 + f] = H[(nodeBase + n) * FF + f];
    }
    __syncthreads();

    const int nl = tid >> 3;       // 0..15
    const int h = tid & 7;         // 0..7
    const int n = nodeBase + nl;

    float hw[8];
#pragma unroll
    for (int u = 0; u < 8; u++) hw[u] = 0.f;

#pragma unroll 4
    for (int f = 0; f < FF; f++) {
        float hv = sH[nl * 129 + f];
        float4 w0 = *reinterpret_cast<const float4*>(&sW[h * WS + f * 8]);
        float4 w1 = *reinterpret_cast<const float4*>(&sW[h * WS + f * 8 + 4]);
        hw[0] += hv * w0.x; hw[1] += hv * w0.y; hw[2] += hv * w0.z; hw[3] += hv * w0.w;
        hw[4] += hv * w1.x; hw[5] += hv * w1.y; hw[6] += hv * w1.z; hw[7] += hv * w1.w;
    }

    float el = 0.f, er = 0.f;
#pragma unroll
    for (int u = 0; u < 8; u++) {
        el += hw[u] * sal[h * 8 + u];
        er += hw[u] * sar[h * 8 + u];
    }
    const float s = expf(er);
    g_el[h * NN + n] = el;

#pragma unroll
    for (int u = 0; u < 8; u++) {
        float v = s * hw[u];
        __nv_bfloat16 hi = __float2bfloat16(v);
        float lo = v - __bfloat162float(hi);
        g_Xp[(h * 8 + u) * NN + n] = hi;
        g_Xp[(80 + h * 8 + u) * NN + n] = __float2bfloat16(lo);
    }
    {
        __nv_bfloat16 hi = __float2bfloat16(s);
        float lo = s - __bfloat162float(hi);
        g_Xp[(64 + h) * NN + n] = hi;
        g_Xp[(144 + h) * NN + n] = __float2bfloat16(lo);
    }
    if (h == 0) {
        const __nv_bfloat16 one = __float2bfloat16(1.0f);
        const __nv_bfloat16 zero = __float2bfloat16(0.0f);
        g_Xp[72 * NN + n] = one;        // degree column (hi)
        g_Xp[152 * NN + n] = zero;      // degree column (lo)
#pragma unroll
        for (int c2 = 73; c2 < 80; c2++) {
            g_Xp[c2 * NN + n] = zero;
            g_Xp[(c2 + 80) * NN + n] = zero;
        }
    }
}

// ---------------- bf16 mma helper ----------------
__device__ __forceinline__ void mma16816(float c[4], const uint32_t a[4],
                                         uint32_t b0, uint32_t b1)
{
    asm volatile(
        "mma.sync.aligned.m16n8k16.row.col.f32.bf16.bf16.f32 "
        "{%0,%1,%2,%3}, {%4,%5,%6,%7}, {%8,%9}, {%0,%1,%2,%3};\n"
        : "+f"(c[0]), "+f"(c[1]), "+f"(c[2]), "+f"(c[3])
        : "r"(a[0]), "r"(a[1]), "r"(a[2]), "r"(a[3]), "r"(b0), "r"(b1));
}

// ---------------- main GEMM + fused epilogue ----------------
// grid = 64 CTAs (M-tile 64), 256 threads = 8 warps (2 in M x 4 in N)
__global__ __launch_bounds__(256, 1) void gat_gemm(
    const float* __restrict__ A, float* __restrict__ out)
{
    __shared__ __align__(16) unsigned char smem_raw[64 * 164 * 4];  // 41984 B
    __nv_bfloat16* As = reinterpret_cast<__nv_bfloat16*>(smem_raw); // [64][72]
    __nv_bfloat16* Bs = As + 64 * 72;                               // [160][72] (col-major: [n][k])
    float* Cs = reinterpret_cast<float*>(smem_raw);                  // [64][164]

    const int tid = threadIdx.x;
    const int wid = tid >> 5, lane = tid & 31;
    const int g = lane >> 2, tg = lane & 3;
    const int wm = wid & 1;        // 0..1  (rows 32*wm)
    const int wn = wid >> 1;       // 0..3  (cols 40*wn)
    const int rowBase = blockIdx.x * 64;

    // A loader mapping: 16 consecutive floats per thread
    const int lr = tid >> 2;              // 0..63
    const int lk = (tid & 3) * 16;        // 0,16,32,48
    const float* Abase = A + (size_t)(rowBase + lr) * NN + lk;

    float4 pfA[4];
    uint2 pfB[10];

    // prefetch chunk 0
#pragma unroll
    for (int j = 0; j < 4; j++) pfA[j] = *reinterpret_cast<const float4*>(Abase + j * 4);
#pragma unroll
    for (int it = 0; it < 10; it++) {
        int idx = tid + it * 256;
        int cc = idx >> 4, kk = (idx & 15) << 2;
        pfB[it] = *reinterpret_cast<const uint2*>(g_Xp + cc * NN + kk);
    }

    float acc[2][5][4];
#pragma unroll
    for (int mt = 0; mt < 2; mt++)
#pragma unroll
        for (int nt = 0; nt < 5; nt++)
#pragma unroll
            for (int q = 0; q < 4; q++) acc[mt][nt][q] = 0.f;

    for (int chunk = 0; chunk < NN / KC; chunk++) {
        // ---- store prefetched chunk to smem (A: fp32 -> bf16) ----
#pragma unroll
        for (int j = 0; j < 4; j++) {
            __nv_bfloat162* dst = reinterpret_cast<__nv_bfloat162*>(As + lr * 72 + lk + j * 4);
            dst[0] = __floats2bfloat162_rn(pfA[j].x, pfA[j].y);
            dst[1] = __floats2bfloat162_rn(pfA[j].z, pfA[j].w);
        }
#pragma unroll
        for (int it = 0; it < 10; it++) {
            int idx = tid + it * 256;
            int cc = idx >> 4, kk = (idx & 15) << 2;
            *reinterpret_cast<uint2*>(Bs + cc * 72 + kk) = pfB[it];
        }
        __syncthreads();

        // ---- issue prefetch for next chunk ----
        if (chunk + 1 < NN / KC) {
            int kc2 = (chunk + 1) * KC;
            const float* Anext = Abase + kc2;
#pragma unroll
            for (int j = 0; j < 4; j++) pfA[j] = *reinterpret_cast<const float4*>(Anext + j * 4);
#pragma unroll
            for (int it = 0; it < 10; it++) {
                int idx = tid + it * 256;
                int cc = idx >> 4, kk = (idx & 15) << 2;
                pfB[it] = *reinterpret_cast<const uint2*>(g_Xp + cc * NN + kc2 + kk);
            }
        }

        // ---- MMA over the staged chunk ----
#pragma unroll
        for (int k16 = 0; k16 < KC / 16; k16++) {
            const int kb = k16 * 16;
            uint32_t a[2][4];
#pragma unroll
            for (int mt = 0; mt < 2; mt++) {
                int r = wm * 32 + mt * 16 + g;
                a[mt][0] = *reinterpret_cast<const uint32_t*>(As + r * 72 + kb + tg * 2);
                a[mt][1] = *reinterpret_cast<const uint32_t*>(As + (r + 8) * 72 + kb + tg * 2);
                a[mt][2] = *reinterpret_cast<const uint32_t*>(As + r * 72 + kb + 8 + tg * 2);
                a[mt][3] = *reinterpret_cast<const uint32_t*>(As + (r + 8) * 72 + kb + 8 + tg * 2);
            }
#pragma unroll
            for (int nt = 0; nt < 5; nt++) {
                int col = wn * 40 + nt * 8 + g;
                uint32_t b0 = *reinterpret_cast<const uint32_t*>(Bs + col * 72 + kb + tg * 2);
                uint32_t b1 = *reinterpret_cast<const uint32_t*>(Bs + col * 72 + kb + 8 + tg * 2);
                mma16816(acc[0][nt], a[0], b0, b1);
                mma16816(acc[1][nt], a[1], b0, b1);
            }
        }
        __syncthreads();
    }

    // ---- dump C to smem ----
#pragma unroll
    for (int mt = 0; mt < 2; mt++) {
#pragma unroll
        for (int nt = 0; nt < 5; nt++) {
            int r = wm * 32 + mt * 16 + g;
            int col = wn * 40 + nt * 8 + tg * 2;
            Cs[r * 164 + col]           = acc[mt][nt][0];
            Cs[r * 164 + col + 1]       = acc[mt][nt][1];
            Cs[(r + 8) * 164 + col]     = acc[mt][nt][2];
            Cs[(r + 8) * 164 + col + 1] = acc[mt][nt][3];
        }
    }
    __syncthreads();

    // ---- fused epilogue: 64 rows x 8 heads tasks ----
    for (int t = tid; t < 64 * HEADS; t += 256) {
        int r = t >> 3, h = t & 7;
        int grow = rowBase + r;
        float e = expf(g_el[h * NN + grow]);
        float sden = Cs[r * 164 + 64 + h] + Cs[r * 164 + 144 + h];
        float deg  = Cs[r * 164 + 72] + Cs[r * 164 + 152];
        float denom = ((float)NN - deg) + e * sden;
#pragma unroll
        for (int u = 0; u < 8; u++) {
            float agg = Cs[r * 164 + h * 8 + u] + Cs[r * 164 + 80 + h * 8 + u];
            float v = e * agg / denom;
            out[grow * (HEADS * UU) + h * 8 + u] = (v > 0.f) ? v : expm1f(v);
        }
    }
}

// ---------------- launcher ----------------
extern "C" void kernel_launch(void* const* d_in, const int* in_sizes, int n_in,
                              void* d_out, int out_size)
{
    const float* A  = (const float*)d_in[0];
    const float* H  = (const float*)d_in[1];
    const float* W  = (const float*)d_in[2];
    const float* al = (const float*)d_in[3];
    const float* ar = (const float*)d_in[4];
    float* out = (float*)d_out;

    gat_build<<<NN / 16, 128>>>(H, W, al, ar);
    gat_gemm<<<NN / 64, 256>>>(A, out);
}

// round 2
// speedup vs baseline: 1.6271x; 1.6271x over previous
#include <cuda_runtime.h>
#include <cuda_bf16.h>
#include <cstdint>

// Problem constants (fixed shapes)
#define NN 4096
#define FF 128
#define HEADS 8
#define UU 8
#define NCOL 160        // 80 hi cols + 80 lo cols
#define MT 128          // GEMM M-tile
#define KSPLIT 4        // K-splits
#define KPC 1024        // K per CTA
#define KC 32           // K chunk per pipeline stage

// ---------------- device scratch (no allocations allowed) ----------------
__device__ __nv_bfloat16 g_Xp[NCOL * NN];           // [col][node]
__device__ float g_el[HEADS * NN];                  // e_left per head/node
__device__ float g_part[KSPLIT][NN][NCOL];          // GEMM partials (10.5 MB)

// ---------------- prep kernel: build Xp and e_l ----------------
// block 128 = 16 node-pairs x 8 heads -> 32 nodes/block; grid 128
__global__ __launch_bounds__(128) void gat_build(
    const float* __restrict__ H, const float* __restrict__ W,
    const float* __restrict__ al, const float* __restrict__ ar)
{
    __shared__ float sW[FF * 64];     // [f*64 + h*8 + u] = 32 KB
    __shared__ float sal[64], sar[64];

    const int tid = threadIdx.x;
    for (int i = tid; i < HEADS * FF * UU; i += 128) {
        int h = i >> 10, rem = i & 1023;
        int f = rem >> 3, u = rem & 7;
        sW[f * 64 + h * 8 + u] = W[i];
    }
    if (tid < 64) { sal[tid] = al[tid]; sar[tid] = ar[tid]; }
    __syncthreads();

    const int np = tid >> 3;          // 0..15
    const int h = tid & 7;
    const int n0 = blockIdx.x * 32 + np * 2;

    float hw0[8], hw1[8];
#pragma unroll
    for (int u = 0; u < 8; u++) { hw0[u] = 0.f; hw1[u] = 0.f; }

    const float4* H0 = reinterpret_cast<const float4*>(H + (size_t)n0 * FF);
    const float4* H1 = reinterpret_cast<const float4*>(H + (size_t)(n0 + 1) * FF);

#pragma unroll 2
    for (int fq = 0; fq < FF / 4; fq++) {
        float4 x0 = H0[fq];
        float4 x1 = H1[fq];
        const float xe0[4] = {x0.x, x0.y, x0.z, x0.w};
        const float xe1[4] = {x1.x, x1.y, x1.z, x1.w};
#pragma unroll
        for (int e = 0; e < 4; e++) {
            int f = fq * 4 + e;
            float4 w0 = *reinterpret_cast<const float4*>(sW + f * 64 + h * 8);
            float4 w1 = *reinterpret_cast<const float4*>(sW + f * 64 + h * 8 + 4);
            float a = xe0[e], b = xe1[e];
            hw0[0] += a * w0.x; hw0[1] += a * w0.y; hw0[2] += a * w0.z; hw0[3] += a * w0.w;
            hw0[4] += a * w1.x; hw0[5] += a * w1.y; hw0[6] += a * w1.z; hw0[7] += a * w1.w;
            hw1[0] += b * w0.x; hw1[1] += b * w0.y; hw1[2] += b * w0.z; hw1[3] += b * w0.w;
            hw1[4] += b * w1.x; hw1[5] += b * w1.y; hw1[6] += b * w1.z; hw1[7] += b * w1.w;
        }
    }

#pragma unroll
    for (int d = 0; d < 2; d++) {
        const float* hw = d ? hw1 : hw0;
        const int n = n0 + d;
        float el = 0.f, er = 0.f;
#pragma unroll
        for (int u = 0; u < 8; u++) {
            el += hw[u] * sal[h * 8 + u];
            er += hw[u] * sar[h * 8 + u];
        }
        const float s = expf(er);
        g_el[h * NN + n] = el;
#pragma unroll
        for (int u = 0; u < 8; u++) {
            float v = s * hw[u];
            __nv_bfloat16 hi = __float2bfloat16(v);
            float lo = v - __bfloat162float(hi);
            g_Xp[(h * 8 + u) * NN + n] = hi;
            g_Xp[(80 + h * 8 + u) * NN + n] = __float2bfloat16(lo);
        }
        {
            __nv_bfloat16 shi = __float2bfloat16(s);
            float slo = s - __bfloat162float(shi);
            g_Xp[(64 + h) * NN + n] = shi;
            g_Xp[(144 + h) * NN + n] = __float2bfloat16(slo);
        }
        if (h == 0) {
            const __nv_bfloat16 one = __float2bfloat16(1.0f);
            const __nv_bfloat16 zero = __float2bfloat16(0.0f);
            g_Xp[72 * NN + n] = one;
            g_Xp[152 * NN + n] = zero;
#pragma unroll
            for (int c2 = 73; c2 < 80; c2++) {
                g_Xp[c2 * NN + n] = zero;
                g_Xp[(c2 + 80) * NN + n] = zero;
            }
        }
    }
}

// ---------------- bf16 mma helper ----------------
__device__ __forceinline__ void mma16816(float c[4], const uint32_t a[4],
                                         uint32_t b0, uint32_t b1)
{
    asm volatile(
        "mma.sync.aligned.m16n8k16.row.col.f32.bf16.bf16.f32 "
        "{%0,%1,%2,%3}, {%4,%5,%6,%7}, {%8,%9}, {%0,%1,%2,%3};\n"
        : "+f"(c[0]), "+f"(c[1]), "+f"(c[2]), "+f"(c[3])
        : "r"(a[0]), "r"(a[1]), "r"(a[2]), "r"(a[3]), "r"(b0), "r"(b1));
}

// ---------------- GEMM: A[4096x4096] @ Xp[4096x160], K-split partials ----------------
// grid (32, 4): x = M-tile, y = K-split. 256 threads = 8 warps (2 M x 4 N).
struct GemmCtx {
    const float* Aptr;          // per-thread A source base
    int tid, g, tg, wm, wn;
    int kBase0;
};

__device__ __forceinline__ void gemm_step(
    const GemmCtx& cx, int c,
    __nv_bfloat16* __restrict__ as, __nv_bfloat16* __restrict__ bs,
    float4 (&pac)[4], uint2 (&pb)[5], float (&acc)[4][5][4])
{
    const int tid = cx.tid;
    const int arow = tid >> 1;
    const int akh = (tid & 1) * 16;

    // ---- STS A (fp32 regs -> bf16 smem) ----
#pragma unroll
    for (int j = 0; j < 4; j++) {
        __nv_bfloat162 p0 = __floats2bfloat162_rn(pac[j].x, pac[j].y);
        __nv_bfloat162 p1 = __floats2bfloat162_rn(pac[j].z, pac[j].w);
        uint2 v;
        v.x = *reinterpret_cast<uint32_t*>(&p0);
        v.y = *reinterpret_cast<uint32_t*>(&p1);
        *reinterpret_cast<uint2*>(as + arow * 40 + akh + j * 4) = v;
    }
    // ---- STS B ----
#pragma unroll
    for (int it = 0; it < 5; it++) {
        int idx = tid + it * 256;
        int cc = idx >> 3, ke = (idx & 7) * 4;
        *reinterpret_cast<uint2*>(bs + cc * 40 + ke) = pb[it];
    }
    // ---- LDG next: A 2 chunks ahead, B 1 chunk ahead ----
    if (c + 2 < KPC / KC) {
#pragma unroll
        for (int j = 0; j < 4; j++)
            pac[j] = *reinterpret_cast<const float4*>(cx.Aptr + (c + 2) * KC + j * 4);
    }
    if (c + 1 < KPC / KC) {
#pragma unroll
        for (int it = 0; it < 5; it++) {
            int idx = tid + it * 256;
            int cc = idx >> 3, ke = (idx & 7) * 4;
            pb[it] = *reinterpret_cast<const uint2*>(
                g_Xp + cc * NN + cx.kBase0 + (c + 1) * KC + ke);
        }
    }
    __syncthreads();

    // ---- MMA over staged chunk (2 x k16) ----
#pragma unroll
    for (int k16 = 0; k16 < 2; k16++) {
        const int kb = k16 * 16;
        uint32_t a[4][4];
#pragma unroll
        for (int mt = 0; mt < 4; mt++) {
            int r = cx.wm * 64 + mt * 16 + cx.g;
            a[mt][0] = *reinterpret_cast<const uint32_t*>(as + r * 40 + kb + cx.tg * 2);
            a[mt][1] = *reinterpret_cast<const uint32_t*>(as + (r + 8) * 40 + kb + cx.tg * 2);
            a[mt][2] = *reinterpret_cast<const uint32_t*>(as + r * 40 + kb + 8 + cx.tg * 2);
            a[mt][3] = *reinterpret_cast<const uint32_t*>(as + (r + 8) * 40 + kb + 8 + cx.tg * 2);
        }
#pragma unroll
        for (int nt = 0; nt < 5; nt++) {
            int col = cx.wn * 40 + nt * 8 + cx.g;
            uint32_t b0 = *reinterpret_cast<const uint32_t*>(bs + col * 40 + kb + cx.tg * 2);
            uint32_t b1 = *reinterpret_cast<const uint32_t*>(bs + col * 40 + kb + 8 + cx.tg * 2);
#pragma unroll
            for (int mt = 0; mt < 4; mt++)
                mma16816(acc[mt][nt], a[mt], b0, b1);
        }
    }
}

__global__ __launch_bounds__(256, 1) void gat_gemm(const float* __restrict__ A)
{
    __shared__ __align__(16) __nv_bfloat16 As0[MT * 40];    // 10 KB
    __shared__ __align__(16) __nv_bfloat16 As1[MT * 40];
    __shared__ __align__(16) __nv_bfloat16 Bs0[NCOL * 40];  // 12.5 KB
    __shared__ __align__(16) __nv_bfloat16 Bs1[NCOL * 40];

    GemmCtx cx;
    const int tid = threadIdx.x;
    const int lane = tid & 31, wid = tid >> 5;
    cx.tid = tid;
    cx.g = lane >> 2; cx.tg = lane & 3;
    cx.wm = wid & 1;  cx.wn = wid >> 1;
    const int rowBase = blockIdx.x * MT;
    cx.kBase0 = blockIdx.y * KPC;

    const int arow = tid >> 1;
    const int akh = (tid & 1) * 16;
    cx.Aptr = A + (size_t)(rowBase + arow) * NN + cx.kBase0 + akh;

    float4 pa0[4], pa1[4];
    uint2 pb[5];
    // prologue: chunk0 -> pa0, chunk1 -> pa1, chunk0 B -> pb
#pragma unroll
    for (int j = 0; j < 4; j++) pa0[j] = *reinterpret_cast<const float4*>(cx.Aptr + j * 4);
#pragma unroll
    for (int j = 0; j < 4; j++) pa1[j] = *reinterpret_cast<const float4*>(cx.Aptr + KC + j * 4);
#pragma unroll
    for (int it = 0; it < 5; it++) {
        int idx = tid + it * 256;
        int cc = idx >> 3, ke = (idx & 7) * 4;
        pb[it] = *reinterpret_cast<const uint2*>(g_Xp + cc * NN + cx.kBase0 + ke);
    }

    float acc[4][5][4];
#pragma unroll
    for (int mt = 0; mt < 4; mt++)
#pragma unroll
        for (int nt = 0; nt < 5; nt++)
#pragma unroll
            for (int q = 0; q < 4; q++) acc[mt][nt][q] = 0.f;

    for (int ci = 0; ci < (KPC / KC) / 2; ci++) {
        gemm_step(cx, 2 * ci,     As0, Bs0, pa0, pb, acc);
        gemm_step(cx, 2 * ci + 1, As1, Bs1, pa1, pb, acc);
    }

    // ---- store partials to scratch ----
    float* pp = &g_part[blockIdx.y][0][0];
#pragma unroll
    for (int mt = 0; mt < 4; mt++) {
#pragma unroll
        for (int nt = 0; nt < 5; nt++) {
            int r = rowBase + cx.wm * 64 + mt * 16 + cx.g;
            int col = cx.wn * 40 + nt * 8 + cx.tg * 2;
            float2 v0 = make_float2(acc[mt][nt][0], acc[mt][nt][1]);
            float2 v1 = make_float2(acc[mt][nt][2], acc[mt][nt][3]);
            *reinterpret_cast<float2*>(pp + (size_t)r * NCOL + col) = v0;
            *reinterpret_cast<float2*>(pp + (size_t)(r + 8) * NCOL + col) = v1;
        }
    }
}

// ---------------- epilogue: reduce K-splits + softmax-normalize + elu ----------------
// 32768 threads: thread = (node, head)
__global__ __launch_bounds__(256) void gat_epilogue(float* __restrict__ out)
{
    const int t = blockIdx.x * 256 + threadIdx.x;
    const int n = t >> 3, h = t & 7;

    float4 hi0 = make_float4(0, 0, 0, 0), hi1 = hi0, lo0 = hi0, lo1 = hi0;
    float sden = 0.f, deg = 0.f;
#pragma unroll
    for (int s = 0; s < KSPLIT; s++) {
        const float* base = &g_part[s][n][0];
        float4 a0 = *reinterpret_cast<const float4*>(base + h * 8);
        float4 a1 = *reinterpret_cast<const float4*>(base + h * 8 + 4);
        float4 b0 = *reinterpret_cast<const float4*>(base + 80 + h * 8);
        float4 b1 = *reinterpret_cast<const float4*>(base + 80 + h * 8 + 4);
        hi0.x += a0.x; hi0.y += a0.y; hi0.z += a0.z; hi0.w += a0.w;
        hi1.x += a1.x; hi1.y += a1.y; hi1.z += a1.z; hi1.w += a1.w;
        lo0.x += b0.x; lo0.y += b0.y; lo0.z += b0.z; lo0.w += b0.w;
        lo1.x += b1.x; lo1.y += b1.y; lo1.z += b1.z; lo1.w += b1.w;
        sden += base[64 + h] + base[144 + h];
        deg  += base[72] + base[152];
    }

    const float e = expf(g_el[h * NN + n]);
    const float denom = (float)NN - deg + e * sden;
    const float r = e / denom;

    float v[8];
    v[0] = (hi0.x + lo0.x) * r; v[1] = (hi0.y + lo0.y) * r;
    v[2] = (hi0.z + lo0.z) * r; v[3] = (hi0.w + lo0.w) * r;
    v[4] = (hi1.x + lo1.x) * r; v[5] = (hi1.y + lo1.y) * r;
    v[6] = (hi1.z + lo1.z) * r; v[7] = (hi1.w + lo1.w) * r;

    float4 o0, o1;
    o0.x = v[0] > 0.f ? v[0] : expm1f(v[0]);
    o0.y = v[1] > 0.f ? v[1] : expm1f(v[1]);
    o0.z = v[2] > 0.f ? v[2] : expm1f(v[2]);
    o0.w = v[3] > 0.f ? v[3] : expm1f(v[3]);
    o1.x = v[4] > 0.f ? v[4] : expm1f(v[4]);
    o1.y = v[5] > 0.f ? v[5] : expm1f(v[5]);
    o1.z = v[6] > 0.f ? v[6] : expm1f(v[6]);
    o1.w = v[7] > 0.f ? v[7] : expm1f(v[7]);

    float4* op = reinterpret_cast<float4*>(out + (size_t)n * (HEADS * UU) + h * 8);
    op[0] = o0;
    op[1] = o1;
}

// ---------------- launcher ----------------
extern "C" void kernel_launch(void* const* d_in, const int* in_sizes, int n_in,
                              void* d_out, int out_size)
{
    (void)in_sizes; (void)n_in; (void)out_size;
    const float* A  = (const float*)d_in[0];
    const float* H  = (const float*)d_in[1];
    const float* W  = (const float*)d_in[2];
    const float* al = (const float*)d_in[3];
    const float* ar = (const float*)d_in[4];
    float* out = (float*)d_out;

    gat_build<<<NN / 32, 128>>>(H, W, al, ar);
    dim3 gg(NN / MT, KSPLIT);
    gat_gemm<<<gg, 256>>>(A);
    gat_epilogue<<<NN * HEADS / 256, 256>>>(out);
}